// round 1
// baseline (speedup 1.0000x reference)
#include <cuda_runtime.h>

#define B_ 2
#define T_ 2048
#define C_ 2048
#define H_ 16
#define D_ 128
#define QKV_COLS (3 * C_)   // 6144

// Scratch (no cudaMalloc allowed): qkv buffer + attention output buffer.
__device__ float g_qkv[(size_t)B_ * T_ * QKV_COLS];   // ~100.7 MB
__device__ float g_attn[(size_t)B_ * T_ * C_];        // ~33.6 MB

__device__ __forceinline__ float fast_ex2(float x) {
    float y;
    asm("ex2.approx.ftz.f32 %0, %1;" : "=f"(y) : "f"(x));
    return y;
}

// Packed dual-FMA: d.lo += ... ; d.hi += ... (FFMA2, sm_103a)
#define FMA2(d, a, b) asm("fma.rn.f32x2 %0, %1, %2, %0;" : "+l"(d) : "l"(a), "l"(b))
#define UNPACK2(x, y, p) asm("mov.b64 {%0,%1}, %2;" : "=f"(x), "=f"(y) : "l"(p))

// ---------------------------------------------------------------------------
// GEMM: C[M,N] = A[M,K] @ B[K,N], row-major, M%128==0, N%128==0, K%8==0.
// 128x128x8 tile, 256 threads, 8x8 per thread, inner loop = LDS.128 + FFMA2.
// A stored in shared with each value DUPLICATED -> (a,a) pairs read directly
// as 64-bit operands (no pack MOVs in the hot loop).
// ---------------------------------------------------------------------------
__global__ __launch_bounds__(256, 2)
void gemm128(const float* __restrict__ A, const float* __restrict__ Bm,
             float* __restrict__ Cm, int M, int N, int K)
{
    __shared__ __align__(16) float As2[8][256];  // [k][2*m], duplicated pairs
    __shared__ __align__(16) float Bs[8][128];   // [k][n]

    const int tid = threadIdx.x;
    const int ty = tid >> 4, tx = tid & 15;
    const int m0 = blockIdx.y << 7, n0 = blockIdx.x << 7;

    const int arow = tid >> 1;            // 0..127
    const int ak4  = (tid & 1) << 2;      // 0 or 4
    const int brow = tid >> 5;            // 0..7
    const int bc4  = (tid & 31) << 2;     // 0..124

    const float* Ag = A + (size_t)(m0 + arow) * K + ak4;
    const float* Bg = Bm + (size_t)brow * N + n0 + bc4;

    unsigned long long acc[8][4];
#pragma unroll
    for (int i = 0; i < 8; i++)
#pragma unroll
        for (int p = 0; p < 4; p++) acc[i][p] = 0ull;

    const int nk = K >> 3;
    float4 av = *(const float4*)Ag;
    float4 bv = *(const float4*)Bg;

    for (int t = 0; t < nk; ++t) {
        // stage current tile into shared
        *(float2*)&As2[ak4 + 0][2 * arow] = make_float2(av.x, av.x);
        *(float2*)&As2[ak4 + 1][2 * arow] = make_float2(av.y, av.y);
        *(float2*)&As2[ak4 + 2][2 * arow] = make_float2(av.z, av.z);
        *(float2*)&As2[ak4 + 3][2 * arow] = make_float2(av.w, av.w);
        *(float4*)&Bs[brow][bc4] = bv;
        __syncthreads();

        if (t + 1 < nk) {  // register prefetch of next tile
            av = *(const float4*)(Ag + (size_t)(t + 1) * 8);
            bv = *(const float4*)(Bg + (size_t)(t + 1) * 8 * N);
        }

#pragma unroll
        for (int k = 0; k < 8; k++) {
            const unsigned long long* ap0 =
                (const unsigned long long*)&As2[k][8 * ty];
            const unsigned long long* ap1 =
                (const unsigned long long*)&As2[k][128 + 8 * ty];
            unsigned long long a[8];
            a[0] = ap0[0]; a[1] = ap0[1]; a[2] = ap0[2]; a[3] = ap0[3];
            a[4] = ap1[0]; a[5] = ap1[1]; a[6] = ap1[2]; a[7] = ap1[3];

            const unsigned long long* bp0 =
                (const unsigned long long*)&Bs[k][4 * tx];
            const unsigned long long* bp1 =
                (const unsigned long long*)&Bs[k][64 + 4 * tx];
            unsigned long long b0 = bp0[0], b1 = bp0[1];
            unsigned long long b2 = bp1[0], b3 = bp1[1];

#pragma unroll
            for (int i = 0; i < 8; i++) {
                FMA2(acc[i][0], a[i], b0);
                FMA2(acc[i][1], a[i], b1);
                FMA2(acc[i][2], a[i], b2);
                FMA2(acc[i][3], a[i], b3);
            }
        }
        __syncthreads();
    }

    // epilogue
#pragma unroll
    for (int i = 0; i < 8; i++) {
        const int row = m0 + ((i < 4) ? (4 * ty + i) : (64 + 4 * ty + (i - 4)));
        float x0, x1, x2, x3;
        UNPACK2(x0, x1, acc[i][0]);
        UNPACK2(x2, x3, acc[i][1]);
        *(float4*)&Cm[(size_t)row * N + n0 + 4 * tx] = make_float4(x0, x1, x2, x3);
        UNPACK2(x0, x1, acc[i][2]);
        UNPACK2(x2, x3, acc[i][3]);
        *(float4*)&Cm[(size_t)row * N + n0 + 64 + 4 * tx] = make_float4(x0, x1, x2, x3);
    }
}

// ---------------------------------------------------------------------------
// RoPE in-place on q and k slices of g_qkv. One thread per (b,t,h,d<64) pair.
// ---------------------------------------------------------------------------
__global__ void rope_kernel(const float* __restrict__ cosT,
                            const float* __restrict__ sinT)
{
    const int idx = blockIdx.x * 256 + threadIdx.x;     // < 2^22
    const int d = idx & 63;
    const int h = (idx >> 6) & 15;
    const int t = (idx >> 10) & 2047;
    const int b = idx >> 21;

    const float c = cosT[t * 64 + d];
    const float s = sinT[t * 64 + d];

    size_t base = ((size_t)(b * T_ + t)) * QKV_COLS + h * D_ + d;
    // q
    float x0 = g_qkv[base], x1 = g_qkv[base + 64];
    g_qkv[base]      = x0 * c - x1 * s;
    g_qkv[base + 64] = x1 * c + x0 * s;
    // k
    base += C_;
    x0 = g_qkv[base]; x1 = g_qkv[base + 64];
    g_qkv[base]      = x0 * c - x1 * s;
    g_qkv[base + 64] = x1 * c + x0 * s;
}

// ---------------------------------------------------------------------------
// Flash attention (causal), fp32. One block = (b, h, 64-row q tile).
// 64x64 S tiles, online softmax, O accumulated in registers (4x8 per thread).
// K kept transposed in smem ([d][tok]) for conflict-free LDS.128 in S-gemm.
// ---------------------------------------------------------------------------
#define ATTN_SMEM_FLOATS (64 * 132 + 128 * 68 + 64 * 132 + 64 * 68 + 192)

__global__ __launch_bounds__(256)
void attn_kernel(float* __restrict__ outp)
{
    extern __shared__ float sm[];
    float* Qs  = sm;                 // [64][132]
    float* Ks  = Qs + 64 * 132;      // [128][68]  (transposed: [d][tok])
    float* Vs  = Ks + 128 * 68;      // [64][132]
    float* Ss  = Vs + 64 * 132;      // [64][68]
    float* msh = Ss + 64 * 68;       // [64]
    float* lsh = msh + 64;           // [64]
    float* ash = lsh + 64;           // [64]

    const int tid = threadIdx.x;
    const int lin = blockIdx.x;
    const int it  = 31 - (lin & 31);         // heavy q-tiles first
    const int bh  = lin >> 5;
    const int b   = bh >> 4, h = bh & 15;

    const float sl2e = 1.4426950408889634f / sqrtf(128.0f);  // log2(e)/sqrt(D)

    // Load Q tile (64 x 128)
    {
        const int r = tid >> 2;
        const size_t gbase = ((size_t)(b * T_ + it * 64 + r)) * QKV_COLS + h * D_;
#pragma unroll
        for (int i = 0; i < 8; i++) {
            const int d0 = 4 * ((tid & 3) + 4 * i);
            *(float4*)&Qs[r * 132 + d0] = *(const float4*)&g_qkv[gbase + d0];
        }
    }
    if (tid < 64) { msh[tid] = -1e30f; lsh[tid] = 0.0f; }

    float o[4][8];
#pragma unroll
    for (int i = 0; i < 4; i++)
#pragma unroll
        for (int j = 0; j < 8; j++) o[i][j] = 0.0f;

    const int ty = tid >> 4, tx = tid & 15;

    for (int jt = 0; jt <= it; ++jt) {
        __syncthreads();  // protect smem reuse (and Q/m init on first iter)

        // Load K (transposed) and V tiles
        {
            const int tok = tid >> 2;
            const size_t kbase =
                ((size_t)(b * T_ + jt * 64 + tok)) * QKV_COLS + C_ + h * D_;
#pragma unroll
            for (int i = 0; i < 8; i++) {
                const int d0 = 4 * ((tid & 3) + 4 * i);
                const float4 kv = *(const float4*)&g_qkv[kbase + d0];
                Ks[(d0 + 0) * 68 + tok] = kv.x;
                Ks[(d0 + 1) * 68 + tok] = kv.y;
                Ks[(d0 + 2) * 68 + tok] = kv.z;
                Ks[(d0 + 3) * 68 + tok] = kv.w;
                *(float4*)&Vs[tok * 132 + d0] =
                    *(const float4*)&g_qkv[kbase + C_ + d0];
            }
        }
        __syncthreads();

        // S = Q @ K^T  (64x64), thread computes 4x4
        float sacc[4][4];
#pragma unroll
        for (int i = 0; i < 4; i++)
#pragma unroll
            for (int j = 0; j < 4; j++) sacc[i][j] = 0.0f;

#pragma unroll 2
        for (int kk = 0; kk < 128; kk += 4) {
            float qreg[4][4];
#pragma unroll
            for (int i = 0; i < 4; i++) {
                const float4 t4 = *(const float4*)&Qs[(4 * ty + i) * 132 + kk];
                qreg[i][0] = t4.x; qreg[i][1] = t4.y;
                qreg[i][2] = t4.z; qreg[i][3] = t4.w;
            }
#pragma unroll
            for (int e = 0; e < 4; e++) {
                const float4 kv = *(const float4*)&Ks[(kk + e) * 68 + 4 * tx];
                const float kr0 = kv.x, kr1 = kv.y, kr2 = kv.z, kr3 = kv.w;
#pragma unroll
                for (int i = 0; i < 4; i++) {
                    sacc[i][0] += qreg[i][e] * kr0;
                    sacc[i][1] += qreg[i][e] * kr1;
                    sacc[i][2] += qreg[i][e] * kr2;
                    sacc[i][3] += qreg[i][e] * kr3;
                }
            }
        }
#pragma unroll
        for (int i = 0; i < 4; i++)
            *(float4*)&Ss[(4 * ty + i) * 68 + 4 * tx] =
                make_float4(sacc[i][0], sacc[i][1], sacc[i][2], sacc[i][3]);
        __syncthreads();

        // Online softmax: 4 threads per row, 16 cols each
        {
            const int row = tid >> 2, sub = tid & 3;
            const bool diag = (jt == it);
            const int cmax = diag ? (row + 1) : 64;  // cols < cmax are live
            const int cbase = sub * 16;

            float mloc = -1e30f;
#pragma unroll
            for (int jj = 0; jj < 16; jj++) {
                const int col = cbase + jj;
                const float s = Ss[row * 68 + col];
                if (col < cmax) mloc = fmaxf(mloc, s);
            }
            mloc = fmaxf(mloc, __shfl_xor_sync(0xffffffffu, mloc, 1));
            mloc = fmaxf(mloc, __shfl_xor_sync(0xffffffffu, mloc, 2));

            const float mold = msh[row];
            const float mnew = fmaxf(mold, mloc);

            float psum = 0.0f;
#pragma unroll
            for (int jj = 0; jj < 16; jj++) {
                const int col = cbase + jj;
                const float s = Ss[row * 68 + col];
                const float p =
                    (col < cmax) ? fast_ex2((s - mnew) * sl2e) : 0.0f;
                Ss[row * 68 + col] = p;
                psum += p;
            }
            psum += __shfl_xor_sync(0xffffffffu, psum, 1);
            psum += __shfl_xor_sync(0xffffffffu, psum, 2);

            if (sub == 0) {
                const float alpha = fast_ex2((mold - mnew) * sl2e);
                lsh[row] = lsh[row] * alpha + psum;
                msh[row] = mnew;
                ash[row] = alpha;
            }
        }
        __syncthreads();

        // O = O*alpha + P @ V
#pragma unroll
        for (int i = 0; i < 4; i++) {
            const float al = ash[4 * ty + i];
#pragma unroll
            for (int j = 0; j < 8; j++) o[i][j] *= al;
        }
#pragma unroll 2
        for (int k = 0; k < 64; k++) {
            const float4 v0 = *(const float4*)&Vs[k * 132 + 4 * tx];
            const float4 v1 = *(const float4*)&Vs[k * 132 + 64 + 4 * tx];
#pragma unroll
            for (int i = 0; i < 4; i++) {
                const float p = Ss[(4 * ty + i) * 68 + k];
                o[i][0] += p * v0.x; o[i][1] += p * v0.y;
                o[i][2] += p * v0.z; o[i][3] += p * v0.w;
                o[i][4] += p * v1.x; o[i][5] += p * v1.y;
                o[i][6] += p * v1.z; o[i][7] += p * v1.w;
            }
        }
    }

    // Normalize and write out (layout [b*T + q, h*D + d])
#pragma unroll
    for (int i = 0; i < 4; i++) {
        const int r = 4 * ty + i;
        const float inv = 1.0f / lsh[r];
        const size_t obase =
            ((size_t)(b * T_ + it * 64 + r)) * C_ + h * D_ + 4 * tx;
        *(float4*)&outp[obase] =
            make_float4(o[i][0] * inv, o[i][1] * inv, o[i][2] * inv, o[i][3] * inv);
        *(float4*)&outp[obase + 64] =
            make_float4(o[i][4] * inv, o[i][5] * inv, o[i][6] * inv, o[i][7] * inv);
    }
}

// ---------------------------------------------------------------------------
extern "C" void kernel_launch(void* const* d_in, const int* in_sizes, int n_in,
                              void* d_out, int out_size)
{
    const float* x     = (const float*)d_in[0];
    const float* w_qkv = (const float*)d_in[1];
    const float* w_out = (const float*)d_in[2];
    const float* cosT  = (const float*)d_in[3];
    const float* sinT  = (const float*)d_in[4];
    float* out = (float*)d_out;

    float* qkv;  cudaGetSymbolAddress((void**)&qkv, g_qkv);
    float* attn; cudaGetSymbolAddress((void**)&attn, g_attn);

    // 1) QKV projection: [4096,2048] @ [2048,6144]
    {
        dim3 grid(QKV_COLS / 128, (B_ * T_) / 128);
        gemm128<<<grid, 256>>>(x, w_qkv, qkv, B_ * T_, QKV_COLS, C_);
    }

    // 2) RoPE on q,k
    rope_kernel<<<(B_ * T_ * H_ * 64) / 256, 256>>>(cosT, sinT);

    // 3) Causal flash attention
    {
        const size_t smem = (size_t)ATTN_SMEM_FLOATS * sizeof(float);
        cudaFuncSetAttribute(attn_kernel,
                             cudaFuncAttributeMaxDynamicSharedMemorySize,
                             (int)smem);
        attn_kernel<<<B_ * H_ * 32, 256, smem>>>(attn);
    }

    // 4) Output projection: [4096,2048] @ [2048,2048]
    {
        dim3 grid(C_ / 128, (B_ * T_) / 128);
        gemm128<<<grid, 256>>>(attn, w_out, out, B_ * T_, C_, C_);
    }
}